// round 7
// baseline (speedup 1.0000x reference)
#include <cuda_runtime.h>
#include <cstdint>

// dct: [16, 64, 256, 256] fp32, mean/std: [64] fp32, out: [16, 1, 2048, 2048] fp32
#define HW      65536        // 256*256
#define OUTW    2048

__device__ __forceinline__ void cp_async16(uint32_t dst, const void* src) {
    asm volatile("cp.async.cg.shared.global [%0], [%1], 16;" :: "r"(dst), "l"(src));
}
__device__ __forceinline__ void cp_commit() {
    asm volatile("cp.async.commit_group;");
}
__device__ __forceinline__ void cp_wait3() {
    asm volatile("cp.async.wait_group 3;" ::: "memory");
}

__global__ __launch_bounds__(256, 2) void idct_kernel(
    const float* __restrict__ dct,
    const float* __restrict__ mean_,
    const float* __restrict__ std_,
    float* __restrict__ out)
{
    // 4-deep pipeline of chunks; chunk u = channels u*8..u*8+7 for this CTA's
    // 256 consecutive positions. One chunk = 8 x 256 floats = 8KB.
    __shared__ float sbuf[4][8][256];
    __shared__ float s_hx[8][4];     // 0.5*c_u*cos((2xp+1)u pi/16), xp=0..3
    __shared__ float s_hy[8][4];     // same /255 for y pass
    __shared__ float s_std[64];
    __shared__ float s_mean[64];

    int tid = threadIdx.x;
    if (tid < 64) {
        int u = tid >> 3, x = tid & 7;
        float c = (u == 0) ? 0.70710678118654752440f : 1.0f;
        float h = cospif((float)((2 * x + 1) * u) * (1.0f / 16.0f));
        float v = 0.5f * c * h;
        if (x < 4) {
            s_hx[u][x] = v;
            s_hy[u][x] = v * (1.0f / 255.0f);
        }
        s_std[tid]  = std_[tid];
        s_mean[tid] = mean_[tid];
    }
    __syncthreads();

    unsigned gid = blockIdx.x * 256u + (unsigned)tid;
    unsigned b   = gid >> 16;
    unsigned pos = gid & 65535u;                      // h*256 + w
    unsigned posbase = (blockIdx.x * 256u) & 65535u;  // CTA-uniform (256 | 65536)
    const float* src_base = dct + (size_t)b * 64u * HW + posbase;

    uint32_t sb = (uint32_t)__cvta_generic_to_shared(&sbuf[0][0][0]);

    // Issue one 8KB chunk: 512 x 16B units, 2 per thread. Unit j covers
    // channel row j>>6, float columns (j&63)*4 .. +3 of the CTA's pos range.
    auto issue_chunk = [&](int c) {
        #pragma unroll
        for (int k = 0; k < 2; k++) {
            int j = tid + k * 256;
            const float* g = src_base + (size_t)(c * 8 + (j >> 6)) * HW + (j & 63) * 4;
            cp_async16(sb + (uint32_t)((c & 3) * 8192 + j * 16), g);
        }
    };

    // Prologue: 4 chunks in flight (64KB/SM with 2 CTAs)
    #pragma unroll
    for (int c = 0; c < 4; c++) { issue_chunk(c); cp_commit(); }

    // x-pass accumulators: rows xp = E+O, rows 7-xp = E-O. K folded into E.
    const float K = 128.0f / 255.0f;
    float E[4][8], O[4][8];
    #pragma unroll
    for (int xp = 0; xp < 4; xp++)
        #pragma unroll
        for (int y = 0; y < 8; y++) { E[xp][y] = K; O[xp][y] = 0.0f; }

    #pragma unroll
    for (int u = 0; u < 8; u++) {
        cp_wait3();            // chunk u complete (one group retires per iter)
        __syncthreads();

        // destandardize + y-pass from smem
        float t[8];
        #pragma unroll
        for (int v = 0; v < 8; v++)
            t[v] = fmaf(sbuf[u & 3][v][tid], s_std[u * 8 + v], s_mean[u * 8 + v]);

        float ty[8];
        #pragma unroll
        for (int yp = 0; yp < 4; yp++) {
            float te = 0.0f, to = 0.0f;
            #pragma unroll
            for (int vp = 0; vp < 4; vp++) {
                te = fmaf(s_hy[2 * vp    ][yp], t[2 * vp    ], te);
                to = fmaf(s_hy[2 * vp + 1][yp], t[2 * vp + 1], to);
            }
            ty[yp]     = te + to;
            ty[7 - yp] = te - to;
        }

        __syncthreads();       // all reads of buf[u&3] done before refill

        if (u + 4 < 8) issue_chunk(u + 4);
        cp_commit();           // empty groups in tail keep wait_group math valid

        // x-pass: even u -> E, odd u -> O (compile-time via unroll)
        #pragma unroll
        for (int xp = 0; xp < 4; xp++) {
            float w = s_hx[u][xp];
            if ((u & 1) == 0) {
                #pragma unroll
                for (int y = 0; y < 8; y++) E[xp][y] = fmaf(w, ty[y], E[xp][y]);
            } else {
                #pragma unroll
                for (int y = 0; y < 8; y++) O[xp][y] = fmaf(w, ty[y], O[xp][y]);
            }
        }
    }

    // Write 8x8 pixel block: two STG.128 per row.
    unsigned hh = pos >> 8, ww = pos & 255u;
    float* dst = out + (size_t)b * ((size_t)OUTW * OUTW)
                     + (size_t)hh * 8 * OUTW + (size_t)ww * 8;

    #pragma unroll
    for (int xp = 0; xp < 4; xp++) {
        float4 a, bq;
        a.x  = E[xp][0] + O[xp][0];  a.y  = E[xp][1] + O[xp][1];
        a.z  = E[xp][2] + O[xp][2];  a.w  = E[xp][3] + O[xp][3];
        bq.x = E[xp][4] + O[xp][4];  bq.y = E[xp][5] + O[xp][5];
        bq.z = E[xp][6] + O[xp][6];  bq.w = E[xp][7] + O[xp][7];
        *(float4*)(dst + (size_t)xp * OUTW)     = a;
        *(float4*)(dst + (size_t)xp * OUTW + 4) = bq;

        float4 c4, d4;
        c4.x = E[xp][0] - O[xp][0];  c4.y = E[xp][1] - O[xp][1];
        c4.z = E[xp][2] - O[xp][2];  c4.w = E[xp][3] - O[xp][3];
        d4.x = E[xp][4] - O[xp][4];  d4.y = E[xp][5] - O[xp][5];
        d4.z = E[xp][6] - O[xp][6];  d4.w = E[xp][7] - O[xp][7];
        *(float4*)(dst + (size_t)(7 - xp) * OUTW)     = c4;
        *(float4*)(dst + (size_t)(7 - xp) * OUTW + 4) = d4;
    }
}

extern "C" void kernel_launch(void* const* d_in, const int* in_sizes, int n_in,
                              void* d_out, int out_size)
{
    (void)in_sizes; (void)n_in; (void)out_size;
    const float* dct   = (const float*)d_in[0];
    const float* mean_ = (const float*)d_in[1];
    const float* std_  = (const float*)d_in[2];
    float* out = (float*)d_out;
    // 16*256*256 = 1,048,576 blocks of 8x8 pixels, 1 thread each.
    idct_kernel<<<4096, 256>>>(dct, mean_, std_, out);
}

// round 8
// speedup vs baseline: 1.2379x; 1.2379x over previous
#include <cuda_runtime.h>
#include <cstdint>

// dct: [16, 64, 256, 256] fp32, mean/std: [64] fp32, out: [16, 1, 2048, 2048] fp32
#define HW      65536        // 256*256
#define OUTW    2048

// Dynamic smem layout (floats):
//   [0, 16384)        sbuf: 8 chunks x 8 channels x 256 positions
//   [16384, +32)      s_hx[8][4]
//   [+32, +64)        s_hy[8][4]
//   [+64, +128)       s_std[64]
//   [+128, +192)      s_mean[64]
#define SBUF_FLOATS   16384
#define SMEM_FLOATS   (SBUF_FLOATS + 192)
#define SMEM_BYTES    (SMEM_FLOATS * 4)

__device__ __forceinline__ void cp_async16(uint32_t dst, const void* src) {
    asm volatile("cp.async.cg.shared.global [%0], [%1], 16;" :: "r"(dst), "l"(src));
}
__device__ __forceinline__ void cp_commit() {
    asm volatile("cp.async.commit_group;");
}
template <int N>
__device__ __forceinline__ void cp_wait() {
    asm volatile("cp.async.wait_group %0;" :: "n"(N) : "memory");
}

// Consume chunk U: destandardize + y-pass butterfly + x-pass accumulate.
template <int U>
__device__ __forceinline__ void consume_chunk(
    const float* sbuf, const float* s_hx, const float* s_hy,
    const float* s_std, const float* s_mean,
    int tid, float E[4][8], float O[4][8])
{
    cp_wait<7 - U>();
    __syncthreads();   // make this chunk's cp.async data CTA-visible

    float t[8];
    #pragma unroll
    for (int v = 0; v < 8; v++)
        t[v] = fmaf(sbuf[U * 2048 + v * 256 + tid],
                    s_std[U * 8 + v], s_mean[U * 8 + v]);

    float ty[8];
    #pragma unroll
    for (int yp = 0; yp < 4; yp++) {
        float te = 0.0f, to = 0.0f;
        #pragma unroll
        for (int vp = 0; vp < 4; vp++) {
            te = fmaf(s_hy[(2 * vp    ) * 4 + yp], t[2 * vp    ], te);
            to = fmaf(s_hy[(2 * vp + 1) * 4 + yp], t[2 * vp + 1], to);
        }
        ty[yp]     = te + to;
        ty[7 - yp] = te - to;
    }

    #pragma unroll
    for (int xp = 0; xp < 4; xp++) {
        float w = s_hx[U * 4 + xp];
        if ((U & 1) == 0) {
            #pragma unroll
            for (int y = 0; y < 8; y++) E[xp][y] = fmaf(w, ty[y], E[xp][y]);
        } else {
            #pragma unroll
            for (int y = 0; y < 8; y++) O[xp][y] = fmaf(w, ty[y], O[xp][y]);
        }
    }
}

__global__ __launch_bounds__(256, 2) void idct_kernel(
    const float* __restrict__ dct,
    const float* __restrict__ mean_,
    const float* __restrict__ std_,
    float* __restrict__ out)
{
    extern __shared__ float smem[];
    float* sbuf   = smem;
    float* s_hx   = smem + SBUF_FLOATS;        // [8][4]
    float* s_hy   = s_hx + 32;                 // [8][4]
    float* s_std  = s_hy + 32;                 // [64]
    float* s_mean = s_std + 64;                // [64]

    int tid = threadIdx.x;

    unsigned gid = blockIdx.x * 256u + (unsigned)tid;
    unsigned b   = gid >> 16;
    unsigned pos = gid & 65535u;                      // h*256 + w
    unsigned posbase = (blockIdx.x * 256u) & 65535u;  // CTA-uniform
    const float* src_base = dct + (size_t)b * 64u * HW + posbase;

    uint32_t sb = (uint32_t)__cvta_generic_to_shared(sbuf);

    // ---- Issue ALL 8 chunks (64KB) up-front: one commit group per chunk ----
    // Unit j of chunk c: channel c*8 + (j>>6), 16B at float col (j&63)*4.
    // A warp's 32 units cover 512B contiguous within one channel row.
    #pragma unroll
    for (int c = 0; c < 8; c++) {
        #pragma unroll
        for (int k = 0; k < 2; k++) {
            int j = tid + k * 256;
            const float* g = src_base + (size_t)(c * 8 + (j >> 6)) * HW + (j & 63) * 4;
            cp_async16(sb + (uint32_t)(c * 8192 + j * 16), g);
        }
        cp_commit();
    }

    // ---- Tables (overlaps with in-flight copies) ----
    if (tid < 64) {
        int u = tid >> 3, x = tid & 7;
        float c = (u == 0) ? 0.70710678118654752440f : 1.0f;
        float h = cospif((float)((2 * x + 1) * u) * (1.0f / 16.0f));
        float v = 0.5f * c * h;
        if (x < 4) {
            s_hx[u * 4 + x] = v;
            s_hy[u * 4 + x] = v * (1.0f / 255.0f);
        }
        s_std[tid]  = std_[tid];
        s_mean[tid] = mean_[tid];
    }
    __syncthreads();

    // ---- Accumulators: rows xp = E+O, rows 7-xp = E-O. K folded into E. ----
    const float K = 128.0f / 255.0f;
    float E[4][8], O[4][8];
    #pragma unroll
    for (int xp = 0; xp < 4; xp++)
        #pragma unroll
        for (int y = 0; y < 8; y++) { E[xp][y] = K; O[xp][y] = 0.0f; }

    consume_chunk<0>(sbuf, s_hx, s_hy, s_std, s_mean, tid, E, O);
    consume_chunk<1>(sbuf, s_hx, s_hy, s_std, s_mean, tid, E, O);
    consume_chunk<2>(sbuf, s_hx, s_hy, s_std, s_mean, tid, E, O);
    consume_chunk<3>(sbuf, s_hx, s_hy, s_std, s_mean, tid, E, O);
    consume_chunk<4>(sbuf, s_hx, s_hy, s_std, s_mean, tid, E, O);
    consume_chunk<5>(sbuf, s_hx, s_hy, s_std, s_mean, tid, E, O);
    consume_chunk<6>(sbuf, s_hx, s_hy, s_std, s_mean, tid, E, O);
    consume_chunk<7>(sbuf, s_hx, s_hy, s_std, s_mean, tid, E, O);

    // ---- Write 8x8 pixel block: two STG.128 per row ----
    unsigned hh = pos >> 8, ww = pos & 255u;
    float* dst = out + (size_t)b * ((size_t)OUTW * OUTW)
                     + (size_t)hh * 8 * OUTW + (size_t)ww * 8;

    #pragma unroll
    for (int xp = 0; xp < 4; xp++) {
        float4 a, bq;
        a.x  = E[xp][0] + O[xp][0];  a.y  = E[xp][1] + O[xp][1];
        a.z  = E[xp][2] + O[xp][2];  a.w  = E[xp][3] + O[xp][3];
        bq.x = E[xp][4] + O[xp][4];  bq.y = E[xp][5] + O[xp][5];
        bq.z = E[xp][6] + O[xp][6];  bq.w = E[xp][7] + O[xp][7];
        *(float4*)(dst + (size_t)xp * OUTW)     = a;
        *(float4*)(dst + (size_t)xp * OUTW + 4) = bq;

        float4 c4, d4;
        c4.x = E[xp][0] - O[xp][0];  c4.y = E[xp][1] - O[xp][1];
        c4.z = E[xp][2] - O[xp][2];  c4.w = E[xp][3] - O[xp][3];
        d4.x = E[xp][4] - O[xp][4];  d4.y = E[xp][5] - O[xp][5];
        d4.z = E[xp][6] - O[xp][6];  d4.w = E[xp][7] - O[xp][7];
        *(float4*)(dst + (size_t)(7 - xp) * OUTW)     = c4;
        *(float4*)(dst + (size_t)(7 - xp) * OUTW + 4) = d4;
    }
}

extern "C" void kernel_launch(void* const* d_in, const int* in_sizes, int n_in,
                              void* d_out, int out_size)
{
    (void)in_sizes; (void)n_in; (void)out_size;
    const float* dct   = (const float*)d_in[0];
    const float* mean_ = (const float*)d_in[1];
    const float* std_  = (const float*)d_in[2];
    float* out = (float*)d_out;

    static bool attr_set = false;
    if (!attr_set) {
        cudaFuncSetAttribute(idct_kernel,
                             cudaFuncAttributeMaxDynamicSharedMemorySize,
                             SMEM_BYTES);
        attr_set = true;
    }
    // 16*256*256 = 1,048,576 blocks of 8x8 pixels, 1 thread each.
    idct_kernel<<<4096, 256, SMEM_BYTES>>>(dct, mean_, std_, out);
}